// round 17
// baseline (speedup 1.0000x reference)
#include <cuda_runtime.h>
#include <cuda_fp16.h>
#include <math.h>
#include <stdint.h>

#define B_  64
#define S_  2048
#define H_  512
#define M_  (B_ * S_)

// ---------------- device scratch (no allocs allowed) ----------------
__device__ __half g_Bf[H_ * H_];           // Wh^T fp16 [n][k]
__device__ float g_comb[B_ * H_];          // dec@Ws + bs + bh + bc
__device__ float g_epart[4 * M_];          // per-nc partial e sums

// ---------------- helpers ----------------
__device__ __forceinline__ uint32_t smem_u32(const void* p) {
    uint32_t a;
    asm("{ .reg .u64 t; cvta.to.shared.u64 t, %1; cvt.u32.u64 %0, t; }" : "=r"(a) : "l"(p));
    return a;
}
// accurate tanh: 2 MUFU, rel err ~1e-7, saturates correctly
__device__ __forceinline__ float tanh_acc(float x) {
    float e = __expf(2.0f * x);
    return 1.0f - __fdividef(2.0f, e + 1.0f);
}
__device__ __forceinline__ void ldsm4(uint32_t* r, uint32_t addr) {
    asm volatile("ldmatrix.sync.aligned.m8n8.x4.shared.b16 {%0,%1,%2,%3}, [%4];"
                 : "=r"(r[0]), "=r"(r[1]), "=r"(r[2]), "=r"(r[3]) : "r"(addr));
}
__device__ __forceinline__ void mma_f16(float* c, const uint32_t* a, uint32_t b0, uint32_t b1) {
    asm volatile(
        "mma.sync.aligned.m16n8k16.row.col.f32.f16.f16.f32 "
        "{%0,%1,%2,%3},{%4,%5,%6,%7},{%8,%9},{%0,%1,%2,%3};"
        : "+f"(c[0]), "+f"(c[1]), "+f"(c[2]), "+f"(c[3])
        : "r"(a[0]), "r"(a[1]), "r"(a[2]), "r"(a[3]), "r"(b0), "r"(b1));
}
__device__ __forceinline__ void cp16(uint32_t dst, const void* src) {
    asm volatile("cp.async.cg.shared.global [%0], [%1], 16;" :: "r"(dst), "l"(src));
}
__device__ __forceinline__ void sts128(uint32_t addr, uint32_t a, uint32_t b,
                                       uint32_t c, uint32_t d) {
    asm volatile("st.shared.v4.b32 [%0], {%1,%2,%3,%4};"
                 :: "r"(addr), "r"(a), "r"(b), "r"(c), "r"(d) : "memory");
}
__device__ __forceinline__ uint32_t h2u(__half2 h) { return *(uint32_t*)&h; }

// ---------------------------------------------------------------------------
// Prologue: bpack (blocks 0..255), dec_comb (256..767). apack is GONE —
// the main kernel converts A fp32->fp16 in registers.
// ---------------------------------------------------------------------------
__global__ __launch_bounds__(256)
void prologue_kernel(const float* __restrict__ Wh,
                     const float* __restrict__ dec,
                     const float* __restrict__ Ws,
                     const float* __restrict__ bs,
                     const float* __restrict__ bh,
                     const float* __restrict__ bc)
{
    const int bid = blockIdx.x;
    const int tid = threadIdx.x;
    __shared__ float dh[H_];
    __shared__ float red[4][64];

    if (bid < 256) {
        // ---- bpack: Wh [k][n] -> g_Bf [n][k] fp16 (transpose), 2 n per block
        const int n  = bid * 2 + (tid >> 7);
        const int k4 = (tid & 127) * 4;
        __half2 lo = __floats2half2_rn(Wh[(size_t)(k4 + 0) * H_ + n], Wh[(size_t)(k4 + 1) * H_ + n]);
        __half2 hi = __floats2half2_rn(Wh[(size_t)(k4 + 2) * H_ + n], Wh[(size_t)(k4 + 3) * H_ + n]);
        *(uint2*)(g_Bf + (size_t)n * H_ + k4) = make_uint2(h2u(lo), h2u(hi));
    } else {
        // ---- dec_comb: comb[b][n] = dec[b] @ Ws[:,n] + bs + bh + bc ----
        const int id = bid - 256;          // 0..511
        const int b  = id >> 3;
        const int nh = id & 7;

        dh[tid]       = dec[b * H_ + tid];
        dh[tid + 256] = dec[b * H_ + tid + 256];
        __syncthreads();

        const int nl = tid & 63;
        const int n  = nh * 64 + nl;
        const int ks = tid >> 6;
        float acc = 0.f;
        #pragma unroll 8
        for (int h = ks * 128; h < ks * 128 + 128; ++h)
            acc = fmaf(dh[h], Ws[(size_t)h * H_ + n], acc);
        red[ks][nl] = acc;
        __syncthreads();
        if (ks == 0) {
            float s = red[0][nl] + red[1][nl] + red[2][nl] + red[3][nl];
            g_comb[b * H_ + n] = s + bs[n] + bh[n] + bc[n];
        }
    }
}

// ---------------------------------------------------------------------------
// Main: 128x128x512 fp16 HMMA GEMM; A converted fp32->fp16 IN REGISTERS
// (LDG -> CVT -> STS; zero extra smem-port traffic vs cp.async fp16).
// grid (4 nc, 1024 m-tiles), 256 threads = 8 warps (warpM 0..1 x warpN 0..3)
// warp tile 64x32; k-chunk 64; 3-stage pipeline, fully unrolled; 2 CTAs/SM.
// ---------------------------------------------------------------------------
#define MAT_BYTES   16384                 // 128 rows x 128B (swizzled, no pad)
#define STAGE_BYTES (2 * MAT_BYTES)       // 32768 (A|B)
#define OFF_COMB  (3 * STAGE_BYTES)       // 98304
#define OFF_WC    (OFF_COMB + 512)
#define OFF_VW    (OFF_WC + 512)
#define OFF_ERED  (OFF_VW + 512)          // 99840: 128 rows x 4 warpN floats
#define SMEM_DYN  (OFF_ERED + 128 * 4 * 4)   // 101888

// swizzled byte offset of (row r, 16B-chunk c) within a 128x128B matrix
#define SWZOFF(r, c) ((uint32_t)((r) * 128 + ((((c) ^ ((r) & 7))) << 4)))

__global__ __launch_bounds__(256, 2)
void attn_hmma_kernel(const float* __restrict__ enc,
                      const float* __restrict__ cov,
                      const float* __restrict__ Wc,
                      const float* __restrict__ v_w)
{
    extern __shared__ char sm[];
    const uint32_t sbase = smem_u32(sm);
    const int tid  = threadIdx.x;
    const int wid  = tid >> 5;
    const int lane = tid & 31;
    const int nc     = blockIdx.x;          // 0..3 (fast-varying: enc L2 reuse)
    const int mBase  = blockIdx.y * 128;
    const int ncBase = nc * 128;
    const int b      = mBase >> 11;

    // epilogue constants for this n-chunk (ordered before use by iter-0 sync)
    if (tid < 128) {
        ((float*)(sm + OFF_COMB))[tid] = g_comb[b * H_ + ncBase + tid];
        ((float*)(sm + OFF_WC))[tid]   = Wc[ncBase + tid];
        ((float*)(sm + OFF_VW))[tid]   = v_w[ncBase + tid];
    }

    // thread covers rows (tid>>3)+32p, 16B-fp16-chunk cc = tid&7; p = 0..3
    const uint32_t dstA0 = sbase + SWZOFF(tid >> 3, tid & 7);
    const uint32_t dstB0 = dstA0 + MAT_BYTES;
    // A fp32 source: k floats [cc*8, cc*8+8) of chunk -> 2 float4
    const float* srcA32 = enc + (size_t)(mBase + (tid >> 3)) * H_ + (tid & 7) * 8;
    const char*  srcB0  = (const char*)(g_Bf + (size_t)(ncBase + (tid >> 3)) * H_) + (tid & 7) * 16;

// A: LDG 2 float4 for sub-row p of chunk kc into v0,v1
#define LDG_A(kc, p, v0, v1) do { \
    const float* _s = srcA32 + (p) * (32 * H_) + (kc) * 64; \
    v0 = __ldg((const float4*)_s); \
    v1 = __ldg((const float4*)_s + 1); \
} while (0)
// A: convert + STS sub-row p of chunk kc (stage stg)
#define STS_A(kc, stg, p, v0, v1) \
    sts128(dstA0 + (uint32_t)(stg) * STAGE_BYTES + (p) * 4096, \
           h2u(__floats2half2_rn(v0.x, v0.y)), h2u(__floats2half2_rn(v0.z, v0.w)), \
           h2u(__floats2half2_rn(v1.x, v1.y)), h2u(__floats2half2_rn(v1.z, v1.w)))
// B: one cp16 (p = 0..3) of chunk kc (stage stg)
#define CP_B(kc, stg, p) \
    cp16(dstB0 + (uint32_t)(stg) * STAGE_BYTES + (p) * 4096, \
         srcB0 + (p) * 32768 + (kc) * 128)

    const int warpM = wid >> 2;            // 0..1 -> 64 rows
    const int warpN = wid & 3;             // 0..3 -> 32 cols

    // per-s ldsm base offsets; mI/p add a linear 2048B (swizzle term invariant)
    uint32_t offA[4], offB[4];
    {
        const int rowA = warpM * 64 + (lane & 7) + ((lane >> 3) & 1) * 8;
        const int cA   = (lane >> 4);                   // 0..1
        #pragma unroll
        for (int s = 0; s < 4; ++s)
            offA[s] = SWZOFF(rowA, s * 2 + cA);
        const int rowB = warpN * 32 + (lane & 7) + ((lane & 16) ? 8 : 0);
        const int cB   = (lane >> 3) & 1;
        #pragma unroll
        for (int s = 0; s < 4; ++s)
            offB[s] = SWZOFF(rowB, s * 2 + cB);
    }

    float acc[4][4][4];
    #pragma unroll
    for (int i = 0; i < 4; ++i)
        #pragma unroll
        for (int j = 0; j < 4; ++j)
            #pragma unroll
            for (int q = 0; q < 4; ++q) acc[i][j][q] = 0.f;

    // prologue: chunks 0 and 1 -> stages 0 and 1 (A via LDG/STS, B via cp)
    #pragma unroll
    for (int kc = 0; kc < 2; ++kc) {
        #pragma unroll
        for (int p = 0; p < 4; ++p) {
            float4 v0, v1;
            LDG_A(kc, p, v0, v1);
            STS_A(kc, kc, p, v0, v1);
        }
        #pragma unroll
        for (int p = 0; p < 4; ++p) CP_B(kc, kc, p);
        asm volatile("cp.async.commit_group;" ::: "memory");
    }

    #pragma unroll
    for (int c = 0; c < 8; ++c) {
        // B of chunk c complete (groups complete in commit order); A via barrier
        if (c < 7) asm volatile("cp.async.wait_group 1;" ::: "memory");
        else       asm volatile("cp.async.wait_group 0;" ::: "memory");
        __syncthreads();   // single barrier per iteration; publishes STS too

        const uint32_t ab = sbase + (c % 3) * STAGE_BYTES;
        const uint32_t bb = ab + MAT_BYTES;
        const int  nk  = c + 2;            // chunk to prefetch
        const int  nst = (c + 2) % 3;

        // fragment rotation: preload s=0; per s run MMA then load s+1
        uint32_t Af[4][4], Bf[2][4];
        #pragma unroll
        for (int p = 0; p < 2; ++p)    ldsm4(Bf[p], bb + offB[0] + p * 2048);
        #pragma unroll
        for (int mI = 0; mI < 4; ++mI) ldsm4(Af[mI], ab + offA[0] + mI * 2048);

        float4 a0, a1, a2, a3;             // 2-sub-row LDG buffer (16 regs)
        #pragma unroll
        for (int s = 0; s < 4; ++s) {
            // spread A convert + B prefetch of chunk c+2 across the s phases
            if (nk < 8) {
                if (s == 0) { LDG_A(nk, 0, a0, a1); LDG_A(nk, 1, a2, a3); }
                if (s == 1) { STS_A(nk, nst, 0, a0, a1); STS_A(nk, nst, 1, a2, a3); }
                if (s == 2) { LDG_A(nk, 2, a0, a1); LDG_A(nk, 3, a2, a3); }
                if (s == 3) { STS_A(nk, nst, 2, a0, a1); STS_A(nk, nst, 3, a2, a3); }
                CP_B(nk, nst, s);
                if (s == 3) asm volatile("cp.async.commit_group;" ::: "memory");
            }
            #pragma unroll
            for (int mI = 0; mI < 4; ++mI)
                #pragma unroll
                for (int nI = 0; nI < 4; ++nI)
                    mma_f16(acc[mI][nI], Af[mI], Bf[nI >> 1][(nI & 1) * 2], Bf[nI >> 1][(nI & 1) * 2 + 1]);
            if (s < 3) {
                #pragma unroll
                for (int p = 0; p < 2; ++p)    ldsm4(Bf[p], bb + offB[s + 1] + p * 2048);
                #pragma unroll
                for (int mI = 0; mI < 4; ++mI) ldsm4(Af[mI], ab + offA[s + 1] + mI * 2048);
            }
        }
    }
#undef LDG_A
#undef STS_A
#undef CP_B

    // ---- fused epilogue: tanh + v-dot; shuffle-reduce the 4 col-threads,
    //      then smem-reduce the 4 warpN warps ----
    const float* sComb = (const float*)(sm + OFF_COMB);
    const float* sWc   = (const float*)(sm + OFF_WC);
    const float* sVw   = (const float*)(sm + OFF_VW);
    float* ered = (float*)(sm + OFF_ERED);    // [128 rows][4 warpN]

    #pragma unroll
    for (int mI = 0; mI < 4; ++mI) {
        const int mlo = warpM * 64 + mI * 16 + (lane >> 2);
        const float covlo = cov[mBase + mlo];
        const float covhi = cov[mBase + mlo + 8];
        float elo = 0.f, ehi = 0.f;
        #pragma unroll
        for (int nI = 0; nI < 4; ++nI) {
            #pragma unroll
            for (int t = 0; t < 2; ++t) {
                const int n = warpN * 32 + nI * 8 + (lane & 3) * 2 + t;
                const float cb = sComb[n], wc = sWc[n], vw = sVw[n];
                elo = fmaf(vw, tanh_acc(acc[mI][nI][t]     + cb + covlo * wc), elo);
                ehi = fmaf(vw, tanh_acc(acc[mI][nI][t + 2] + cb + covhi * wc), ehi);
            }
        }
        // reduce over lane&3 (the 4 column threads of each row)
        elo += __shfl_xor_sync(0xFFFFFFFFu, elo, 1);
        elo += __shfl_xor_sync(0xFFFFFFFFu, elo, 2);
        ehi += __shfl_xor_sync(0xFFFFFFFFu, ehi, 1);
        ehi += __shfl_xor_sync(0xFFFFFFFFu, ehi, 2);
        if ((lane & 3) == 0) {
            ered[mlo * 4 + warpN]       = elo;
            ered[(mlo + 8) * 4 + warpN] = ehi;
        }
    }
    __syncthreads();
    if (tid < 128) {
        const float s = ered[tid * 4] + ered[tid * 4 + 1] + ered[tid * 4 + 2] + ered[tid * 4 + 3];
        g_epart[nc * M_ + mBase + tid] = s;
    }
}

// ---------------------------------------------------------------------------
// Softmax over S=2048 per batch + coverage update (v_b shift-invariant)
// ---------------------------------------------------------------------------
__global__ __launch_bounds__(256)
void softmax_kernel(const float* __restrict__ cov, float* __restrict__ out)
{
    const int b   = blockIdx.x;
    const int tid = threadIdx.x;
    __shared__ float red[256];

    float local[8];
    float mx = -INFINITY;
    #pragma unroll
    for (int i = 0; i < 8; ++i) {
        const int idx = b * S_ + tid + i * 256;
        local[i] = g_epart[idx] + g_epart[M_ + idx] + g_epart[2 * M_ + idx] + g_epart[3 * M_ + idx];
        mx = fmaxf(mx, local[i]);
    }
    red[tid] = mx;
    __syncthreads();
    for (int s = 128; s > 0; s >>= 1) {
        if (tid < s) red[tid] = fmaxf(red[tid], red[tid + s]);
        __syncthreads();
    }
    const float m = red[0];
    __syncthreads();

    float sum = 0.f;
    #pragma unroll
    for (int i = 0; i < 8; ++i) {
        local[i] = __expf(local[i] - m);
        sum += local[i];
    }
    red[tid] = sum;
    __syncthreads();
    for (int s = 128; s > 0; s >>= 1) {
        if (tid < s) red[tid] += red[tid + s];
        __syncthreads();
    }
    const float inv = 1.0f / red[0];

    #pragma unroll
    for (int i = 0; i < 8; ++i) {
        const int idx = b * S_ + tid + i * 256;
        const float a = local[i] * inv;
        out[idx]      = a;
        out[M_ + idx] = cov[idx] + a;
    }
}

// ---------------------------------------------------------------------------
extern "C" void kernel_launch(void* const* d_in, const int* in_sizes, int n_in,
                              void* d_out, int out_size)
{
    const float* enc = (const float*)d_in[0];
    const float* dec = (const float*)d_in[1];
    const float* cov = (const float*)d_in[2];
    const float* Wh  = (const float*)d_in[3];
    const float* bh  = (const float*)d_in[4];
    const float* Ws  = (const float*)d_in[5];
    const float* bs  = (const float*)d_in[6];
    const float* Wc  = (const float*)d_in[7];
    const float* bc  = (const float*)d_in[8];
    const float* v_w = (const float*)d_in[9];
    float* out = (float*)d_out;

    cudaFuncSetAttribute(attn_hmma_kernel,
                         cudaFuncAttributeMaxDynamicSharedMemorySize, SMEM_DYN);

    prologue_kernel<<<768, 256>>>(Wh, dec, Ws, bs, bh, bc);
    attn_hmma_kernel<<<dim3(4, M_ / 128), 256, SMEM_DYN>>>(enc, cov, Wc, v_w);
    softmax_kernel<<<B_, 256>>>(cov, out);
}